// round 15
// baseline (speedup 1.0000x reference)
#include <cuda_runtime.h>
#include <stdint.h>

// Problem constants (fixed by the reference: B=64, T=2048, D=64, V=100000)
#define BB 64
#define TT 2048
#define DD 64
#define BT (BB * TT)            // 131072

// Output layout (floats), tuple flattened in order:
//   features [B,T,256] @ 0
//   times    [B,T]     @ BT*256
//   delta    [B,T,256] @ BT*256 + BT
//   mask     [B,T,256] @ BT*256 + BT + BT*256
#define OFF_TIMES  (BT * 256)                 // 33554432
#define OFF_DELTA  (OFF_TIMES + BT)           // 33685504
#define OFF_MASK   (OFF_DELTA + BT * 256)     // 67239936

// Beta scratch, TRANSPOSED: g_beta[gw*4 + f] so emit reads one float4.
__device__ float g_beta[4 * BT];

// ---------------------------------------------------------------------------
// Kernel 1: beta linear-recurrence scan, ALL 4 FEATURES per block.
// One 512-thread block per batch b; each thread owns 4 consecutive t and
// carries 4 (A,C) pairs. Output stored as float4 per t (coalesced).
// PDL primary: triggers programmatic launch completion at ENTRY.
// ---------------------------------------------------------------------------
__global__ __launch_bounds__(512) void beta_scan_kernel(
    const int*   __restrict__ cat1,
    const int*   __restrict__ cat2,
    const float* __restrict__ num1,
    const float* __restrict__ num2,
    const float* __restrict__ times)
{
    cudaTriggerProgrammaticLaunchCompletion();

    const int b    = blockIdx.x;        // 0..63
    const int tid  = threadIdx.x;       // 0..511
    const int lane = tid & 31;
    const int wid  = tid >> 5;          // 0..15

    __shared__ float sA[16][4], sC[16][4];

    const float* tr  = times + b * TT;
    const int*   c1r = cat1  + b * TT;
    const int*   c2r = cat2  + b * TT;
    const float* n1r = num1  + b * TT;
    const float* n2r = num2  + b * TT;

    const int t0 = tid * 4;

    // ---- vectorized loads: 4 elems per stream ----
    const float4 tvv = __ldg(reinterpret_cast<const float4*>(tr + t0));
    float tv[4] = {tvv.x, tvv.y, tvv.z, tvv.w};
    float tprev = __shfl_up_sync(0xffffffffu, tv[3], 1);
    if (lane == 0) tprev = (t0 > 0) ? __ldg(tr + t0 - 1) : 0.0f;

    const int4 c1v = __ldg(reinterpret_cast<const int4*>(c1r + t0));
    int g0[4] = {c1v.x, c1v.y, c1v.z, c1v.w};
    int g0p = __shfl_up_sync(0xffffffffu, g0[3], 1);
    if (lane == 0) g0p = (t0 > 0) ? __ldg(c1r + t0 - 1) : 0;

    const int4 c2v = __ldg(reinterpret_cast<const int4*>(c2r + t0));
    int g1[4] = {c2v.x, c2v.y, c2v.z, c2v.w};
    int g1p = __shfl_up_sync(0xffffffffu, g1[3], 1);
    if (lane == 0) g1p = (t0 > 0) ? __ldg(c2r + t0 - 1) : 0;

    const float4 n1v = __ldg(reinterpret_cast<const float4*>(n1r + t0));
    float g2[4] = {n1v.x, n1v.y, n1v.z, n1v.w};
    float g2p = __shfl_up_sync(0xffffffffu, g2[3], 1);
    if (lane == 0) g2p = (t0 > 0) ? __ldg(n1r + t0 - 1) : 0.0f;

    const float4 n2v = __ldg(reinterpret_cast<const float4*>(n2r + t0));
    float g3[4] = {n2v.x, n2v.y, n2v.z, n2v.w};
    float g3p = __shfl_up_sync(0xffffffffu, g3[3], 1);
    if (lane == 0) g3p = (t0 > 0) ? __ldg(n2r + t0 - 1) : 0.0f;

    // ---- per-element coefficients a[f][k], c[f][k] ----
    float a[4][4], c[4][4];
    #pragma unroll
    for (int k = 0; k < 4; ++k) {
        const float tkm1 = (k == 0) ? tprev : tv[k - 1];
        const float p  = (tv[k] != -1.0f) ? 1.0f : 0.0f;
        const float dt = (tv[k] - tkm1) * p;

        const int   v0 = (k == 0) ? g0p : g0[k - 1];
        const int   v1 = (k == 0) ? g1p : g1[k - 1];
        const float v2 = (k == 0) ? g2p : g2[k - 1];
        const float v3 = (k == 0) ? g3p : g3[k - 1];

        a[0][k] = ((v0 != 0 && v0 != -1)         ? 1.0f : 0.0f) * p;
        a[1][k] = ((v1 != 0 && v1 != -1)         ? 1.0f : 0.0f) * p;
        a[2][k] = ((v2 != 0.0f && v2 != -1.0f)   ? 1.0f : 0.0f) * p;
        a[3][k] = ((v3 != 0.0f && v3 != -1.0f)   ? 1.0f : 0.0f) * p;
        c[0][k] = dt; c[1][k] = dt; c[2][k] = dt; c[3][k] = dt;
    }
    if (t0 == 0) {
        #pragma unroll
        for (int f = 0; f < 4; ++f) { a[f][0] = 0.0f; c[f][0] = 0.0f; }
    }

    // ---- sequential composition of this thread's 4 elements, per feature ----
    float A[4], C[4];
    #pragma unroll
    for (int f = 0; f < 4; ++f) {
        A[f] = a[f][0]; C[f] = c[f][0];
        #pragma unroll
        for (int k = 1; k < 4; ++k) {
            C[f] = c[f][k] + a[f][k] * C[f];
            A[f] = a[f][k] * A[f];
        }
    }

    // ---- warp inclusive scan (4 features) ----
    #pragma unroll
    for (int off = 1; off < 32; off <<= 1) {
        #pragma unroll
        for (int f = 0; f < 4; ++f) {
            const float Ap = __shfl_up_sync(0xffffffffu, A[f], off);
            const float Cp = __shfl_up_sync(0xffffffffu, C[f], off);
            if (lane >= off) { C[f] = C[f] + A[f] * Cp; A[f] = A[f] * Ap; }
        }
    }
    if (lane == 31) {
        #pragma unroll
        for (int f = 0; f < 4; ++f) { sA[wid][f] = A[f]; sC[wid][f] = C[f]; }
    }
    __syncthreads();

    // ---- serial exclusive scan over 16 warp aggregates (4 threads) ----
    if (tid < 4) {
        const int f = tid;
        float Ae = 1.0f, Ce = 0.0f;
        #pragma unroll
        for (int i = 0; i < 16; ++i) {
            const float Ai = sA[i][f], Ci = sC[i][f];
            sA[i][f] = Ae; sC[i][f] = Ce;
            Ce = Ci + Ai * Ce;
            Ae = Ai * Ae;
        }
    }
    __syncthreads();

    // ---- thread-exclusive prefix ----
    float x[4];
    #pragma unroll
    for (int f = 0; f < 4; ++f) {
        float Ax = __shfl_up_sync(0xffffffffu, A[f], 1);
        float Cx = __shfl_up_sync(0xffffffffu, C[f], 1);
        if (lane == 0) { Ax = 1.0f; Cx = 0.0f; }
        x[f] = Cx + Ax * sC[wid][f];
    }

    // ---- apply elementwise, store float4 per t (coalesced) ----
    float4* out4 = reinterpret_cast<float4*>(g_beta) + ((size_t)b * TT + t0);
    #pragma unroll
    for (int k = 0; k < 4; ++k) {
        #pragma unroll
        for (int f = 0; f < 4; ++f) x[f] = c[f][k] + a[f][k] * x[f];
        out4[k] = make_float4(x[0], x[1], x[2], x[3]);
    }
}

// ---------------------------------------------------------------------------
// Kernel 2: emit. PDL consumer. TWO consecutive (b,t) per warp to amortize
// the per-warp prologue and double MLP; each warp writes 2KB contiguous per
// output region. Beta-independent work before cudaGridDependencySynchronize;
// delta stores after.
// ---------------------------------------------------------------------------
__global__ void emit_kernel(const int*   __restrict__ cat1,
                            const int*   __restrict__ cat2,
                            const float* __restrict__ num1,
                            const float* __restrict__ num2,
                            const float* __restrict__ times,
                            const float* __restrict__ E1,
                            const float* __restrict__ E2,
                            const float* __restrict__ w1,
                            const float* __restrict__ b1,
                            const float* __restrict__ w2,
                            const float* __restrict__ b2,
                            float* __restrict__ out)
{
    const int wix  = blockIdx.x * (blockDim.x >> 5) + (threadIdx.x >> 5);
    const int gw0  = wix * 2;            // first (b,t)
    const int gw1  = gw0 + 1;            // second (b,t)
    const int lane = threadIdx.x & 31;

    const bool lo = (lane < 16);
    const int  sl = lo ? lane : (lane - 16);   // sub-lane within 16

    // --- beta-independent scalar loads for both (b,t) ---
    const int   c1a = __ldg(cat1 + gw0);
    const int   c1b = __ldg(cat1 + gw1);
    const int   c2a = __ldg(cat2 + gw0);
    const int   c2b = __ldg(cat2 + gw1);
    const float n1a = __ldg(num1 + gw0);
    const float n1b = __ldg(num1 + gw1);
    const float n2a = __ldg(num2 + gw0);
    const float n2b = __ldg(num2 + gw1);
    const float tma = __ldg(times + gw0);
    const float tmb = __ldg(times + gw1);

    // --- gathers for both (b,t): 4 independent LDG.128 in flight ---
    const float4* e1a = reinterpret_cast<const float4*>(E1 + (size_t)c1a * DD);
    const float4* e2a = reinterpret_cast<const float4*>(E2 + (size_t)c2a * DD);
    const float4* e1b = reinterpret_cast<const float4*>(E1 + (size_t)c1b * DD);
    const float4* e2b = reinterpret_cast<const float4*>(E2 + (size_t)c2b * DD);
    const float4 v0a = __ldg(lo ? (e1a + sl) : (e2a + sl));
    const float4 v0b = __ldg(lo ? (e1b + sl) : (e2b + sl));

    const float4* wsrc = lo ? (reinterpret_cast<const float4*>(w1) + sl)
                            : (reinterpret_cast<const float4*>(w2) + sl);
    const float4* osrc = lo ? (reinterpret_cast<const float4*>(b1) + sl)
                            : (reinterpret_cast<const float4*>(b2) + sl);
    const float4 wv = __ldg(wsrc);
    const float4 ov = __ldg(osrc);
    const float nna = lo ? n1a : n2a;
    const float nnb = lo ? n1b : n2b;
    const float4 v1a = make_float4(fmaf(nna, wv.x, ov.x), fmaf(nna, wv.y, ov.y),
                                   fmaf(nna, wv.z, ov.z), fmaf(nna, wv.w, ov.w));
    const float4 v1b = make_float4(fmaf(nnb, wv.x, ov.x), fmaf(nnb, wv.y, ov.y),
                                   fmaf(nnb, wv.z, ov.z), fmaf(nnb, wv.w, ov.w));

    // --- mask lane values ---
    const float mva0 = lo ? ((c1a != 0 && c1a != -1) ? 1.0f : 0.0f)
                          : ((c2a != 0 && c2a != -1) ? 1.0f : 0.0f);
    const float mva1 = lo ? ((n1a != 0.0f && n1a != -1.0f) ? 1.0f : 0.0f)
                          : ((n2a != 0.0f && n2a != -1.0f) ? 1.0f : 0.0f);
    const float mvb0 = lo ? ((c1b != 0 && c1b != -1) ? 1.0f : 0.0f)
                          : ((c2b != 0 && c2b != -1) ? 1.0f : 0.0f);
    const float mvb1 = lo ? ((n1b != 0.0f && n1b != -1.0f) ? 1.0f : 0.0f)
                          : ((n2b != 0.0f && n2b != -1.0f) ? 1.0f : 0.0f);

    float4* feat4  = reinterpret_cast<float4*>(out) + (size_t)gw0 * 64;
    float4* delta4 = reinterpret_cast<float4*>(out + OFF_DELTA) + (size_t)gw0 * 64;
    float4* mask4  = reinterpret_cast<float4*>(out + OFF_MASK)  + (size_t)gw0 * 64;

    // --- beta-independent stores (2KB contiguous per region per warp) ---
    __stcs(feat4 + lane,      v0a);
    __stcs(feat4 + lane + 32, v1a);
    __stcs(feat4 + lane + 64, v0b);
    __stcs(feat4 + lane + 96, v1b);
    __stcs(mask4 + lane,      make_float4(mva0, mva0, mva0, mva0));
    __stcs(mask4 + lane + 32, make_float4(mva1, mva1, mva1, mva1));
    __stcs(mask4 + lane + 64, make_float4(mvb0, mvb0, mvb0, mvb0));
    __stcs(mask4 + lane + 96, make_float4(mvb1, mvb1, mvb1, mvb1));
    if (lane == 0)  __stcs(out + OFF_TIMES + gw0, tma);
    if (lane == 16) __stcs(out + OFF_TIMES + gw1, tmb);

    // --- wait for beta grid completion (HW-backed PDL dependency) ---
    cudaGridDependencySynchronize();

    // --- beta-dependent delta stores ---
    const float4 bea = *reinterpret_cast<const float4*>(g_beta + (size_t)gw0 * 4);
    const float4 beb = *reinterpret_cast<const float4*>(g_beta + (size_t)gw1 * 4);
    const float bva0 = lo ? bea.x : bea.y;
    const float bva1 = lo ? bea.z : bea.w;
    const float bvb0 = lo ? beb.x : beb.y;
    const float bvb1 = lo ? beb.z : beb.w;

    __stcs(delta4 + lane,      make_float4(bva0, bva0, bva0, bva0));
    __stcs(delta4 + lane + 32, make_float4(bva1, bva1, bva1, bva1));
    __stcs(delta4 + lane + 64, make_float4(bvb0, bvb0, bvb0, bvb0));
    __stcs(delta4 + lane + 96, make_float4(bvb1, bvb1, bvb1, bvb1));
}

// ---------------------------------------------------------------------------
// Launch
// Inputs (metadata order): cat1, cat2, num1, num2, event_time, E1, E2,
//                          w1, b1, w2, b2
// ---------------------------------------------------------------------------
extern "C" void kernel_launch(void* const* d_in, const int* in_sizes, int n_in,
                              void* d_out, int out_size)
{
    const int*   cat1  = (const int*)  d_in[0];
    const int*   cat2  = (const int*)  d_in[1];
    const float* num1  = (const float*)d_in[2];
    const float* num2  = (const float*)d_in[3];
    const float* times = (const float*)d_in[4];
    const float* E1    = (const float*)d_in[5];
    const float* E2    = (const float*)d_in[6];
    const float* w1    = (const float*)d_in[7];
    const float* b1    = (const float*)d_in[8];
    const float* w2    = (const float*)d_in[9];
    const float* b2    = (const float*)d_in[10];
    float* out = (float*)d_out;

    // Kernel 1: one 512-thread block per batch, all 4 features together
    beta_scan_kernel<<<BB, 512>>>(cat1, cat2, num1, num2, times);

    // Kernel 2: emit, PDL, 2 (b,t) per warp: 65536 warps, 8 warps/block
    cudaLaunchConfig_t cfg = {};
    cfg.gridDim  = dim3(BT / 16, 1, 1);
    cfg.blockDim = dim3(256, 1, 1);
    cfg.dynamicSmemBytes = 0;
    cfg.stream = 0;  // legacy default stream (the capture stream)

    cudaLaunchAttribute attrs[1];
    attrs[0].id = cudaLaunchAttributeProgrammaticStreamSerialization;
    attrs[0].val.programmaticStreamSerializationAllowed = 1;
    cfg.attrs = attrs;
    cfg.numAttrs = 1;

    cudaLaunchKernelEx(&cfg, emit_kernel,
                       cat1, cat2, num1, num2, times,
                       E1, E2, w1, b1, w2, b2, out);
}